// round 4
// baseline (speedup 1.0000x reference)
#include <cuda_runtime.h>
#include <cuda_fp16.h>
#include <cstdint>

#define IN_F   8192
#define OUT_F  8192
#define NTOK   32
#define NCODE  65536
#define GROUPS (IN_F / 8)   // 1024
#define KSPLIT 4
#define KSEG   (IN_F / KSPLIT)   // 2048
#define NIT    (KSEG / 64)       // 32

// ---------------- device scratch (no allocations allowed) ----------------
__device__ __align__(16) static __half g_cb16[NCODE * 8];        // 1 MB
__device__ __align__(16) static __half g_xh16[NTOK * IN_F];      // 512 KB
__device__ static float g_zpart[KSPLIT][NTOK * OUT_F];           // 4 MB

// ---------------- helpers ----------------
__device__ __forceinline__ uint32_t smem_u32(const void* p) {
    uint32_t a;
    asm("{ .reg .u64 t; cvta.to.shared.u64 t, %1; cvt.u32.u64 %0, t; }"
        : "=r"(a) : "l"(p));
    return a;
}

#define SWZ(off) ((off) ^ (((off) >> 3) & 0x70))

__device__ __forceinline__ void ldmat_x4(uint32_t addr, uint32_t& r0, uint32_t& r1,
                                         uint32_t& r2, uint32_t& r3) {
    asm volatile("ldmatrix.sync.aligned.m8n8.x4.shared.b16 {%0,%1,%2,%3}, [%4];"
                 : "=r"(r0), "=r"(r1), "=r"(r2), "=r"(r3) : "r"(addr));
}
__device__ __forceinline__ void mma16816(float* c, uint32_t a0, uint32_t a1,
                                         uint32_t a2, uint32_t a3,
                                         uint32_t b0, uint32_t b1) {
    asm volatile("mma.sync.aligned.m16n8k16.row.col.f32.f16.f16.f32 "
                 "{%0,%1,%2,%3}, {%4,%5,%6,%7}, {%8,%9}, {%0,%1,%2,%3};"
                 : "+f"(c[0]), "+f"(c[1]), "+f"(c[2]), "+f"(c[3])
                 : "r"(a0), "r"(a1), "r"(a2), "r"(a3), "r"(b0), "r"(b1));
}

// ---------------- K0: codebook fp32 -> fp16 ----------------
__global__ void __launch_bounds__(256) k_cb(const float* __restrict__ cb) {
    int r = blockIdx.x * 256 + threadIdx.x;   // one codebook row each
    const float4* p = reinterpret_cast<const float4*>(cb + (size_t)r * 8);
    float4 a = p[0], b = p[1];
    __half2 h0 = __floats2half2_rn(a.x, a.y);
    __half2 h1 = __floats2half2_rn(a.z, a.w);
    __half2 h2 = __floats2half2_rn(b.x, b.y);
    __half2 h3 = __floats2half2_rn(b.z, b.w);
    uint4 v;
    v.x = *reinterpret_cast<unsigned*>(&h0);
    v.y = *reinterpret_cast<unsigned*>(&h1);
    v.z = *reinterpret_cast<unsigned*>(&h2);
    v.w = *reinterpret_cast<unsigned*>(&h3);
    *reinterpret_cast<uint4*>(g_cb16 + (size_t)r * 8) = v;
}

// ---------------- K1: xh = fwht(x*SU)/sqrt(n), to fp16 ----------------
__global__ void __launch_bounds__(256) k_xh(const float* __restrict__ x,
                                            const float* __restrict__ SU) {
    __shared__ float s[IN_F];
    int t = blockIdx.x;
    const float* xr = x + (size_t)t * IN_F;
    for (int i = threadIdx.x; i < IN_F; i += 256)
        s[i] = xr[i] * SU[i];
    for (int h = 1; h < IN_F; h <<= 1) {
        __syncthreads();
        for (int p = threadIdx.x; p < IN_F / 2; p += 256) {
            int i = 2 * p - (p & (h - 1));
            float a = s[i], b = s[i + h];
            s[i] = a + b;
            s[i + h] = a - b;
        }
    }
    __syncthreads();
    const float sc = 0.011048543456039806f;   // 1/sqrt(8192)
    __half* o = g_xh16 + (size_t)t * IN_F;
    for (int i = threadIdx.x; i < IN_F; i += 256)
        o[i] = __float2half(s[i] * sc);
}

// ---------------- K2: gather-dequant + mma.sync ----------------
// grid (64, KSPLIT): x = output tile of 128 rows, y = K segment of 2048.
// Per iter: K-chunk 64. A tile 128x64 fp16 (16KB, SW128), B tile 32x64 fp16 (4KB).
// Double-buffered, one __syncthreads per iter; gathers for it+1 issued before
// the MMAs of it; indices prefetched two iters ahead.
__global__ void __launch_bounds__(256) k_main(const int* __restrict__ Qidxs) {
    __shared__ __align__(128) unsigned char sm[40960]; // A0,A1 @0/16384; B0,B1 @32768/36864
    const uint32_t sb = smem_u32(sm);
    const int tid = threadIdx.x;
    const int wid = tid >> 5;
    const int lid = tid & 31;
    const int m0 = blockIdx.x * 128;
    const int kbase = blockIdx.y * KSEG;

    const uint4* __restrict__ cbu = reinterpret_cast<const uint4*>(g_cb16);
    const __half* __restrict__ xh = g_xh16;

    const int r0 = tid >> 3;   // 0..31 (row slot & token)
    const int j  = tid & 7;    // 0..7  (16B column within 128B row)

    float c[4][4];
    #pragma unroll
    for (int g = 0; g < 4; ++g)
        #pragma unroll
        for (int i = 0; i < 4; ++i) c[g][i] = 0.0f;

    // ---- index / gather pipeline registers ----
    int q[4], qn[4];
    uint4 w[4];
    uint4 bv;

    const int* qrow = Qidxs + (size_t)(m0 + r0) * GROUPS + j;

    // prologue: indices+gather for it=0, indices for it=1
    {
        int g0 = (kbase) >> 3;
        q[0] = __ldg(qrow + g0);
        q[1] = __ldg(qrow + g0 + 32 * GROUPS);
        q[2] = __ldg(qrow + g0 + 64 * GROUPS);
        q[3] = __ldg(qrow + g0 + 96 * GROUPS);
        w[0] = __ldg(&cbu[q[0]]);
        w[1] = __ldg(&cbu[q[1]]);
        w[2] = __ldg(&cbu[q[2]]);
        w[3] = __ldg(&cbu[q[3]]);
        bv = *reinterpret_cast<const uint4*>(xh + (size_t)r0 * IN_F + kbase + j * 8);
        int g1 = (kbase + 64) >> 3;
        qn[0] = __ldg(qrow + g1);
        qn[1] = __ldg(qrow + g1 + 32 * GROUPS);
        qn[2] = __ldg(qrow + g1 + 64 * GROUPS);
        qn[3] = __ldg(qrow + g1 + 96 * GROUPS);
    }

    // ---- ldmatrix address components (constant per thread) ----
    // A (row-major [m][k]): x4 matrices = (rows0-7,k0-7),(rows8-15,k0-7),
    //                                      (rows0-7,k8-15),(rows8-15,k8-15)
    const int a_row_in_tile = (lid & 7) + ((lid >> 3) & 1) * 8;     // 0..15
    const int a_kb_half     = ((lid >> 4) & 1) * 16;                // byte 0/16
    // B (row-major [n][k], fragment needs pairs contiguous in k -> NON-trans):
    // x4 matrices = (n0-7,k0-7),(n0-7,k8-15),(n8-15,k0-7),(n8-15,k8-15)
    const int b_mat  = lid >> 3;                                    // 0..3
    const int b_nrow = ((b_mat >> 1) * 8) + (lid & 7);              // 0..15
    const int b_kb   = (b_mat & 1) * 16;                            // byte 0/16
    const uint32_t b_base = ((uint32_t)b_nrow << 7) + (uint32_t)b_kb;

    for (int it = 0; it < NIT; ++it) {
        const int s = it & 1;
        unsigned char* Ap = sm + s * 16384;
        unsigned char* Bp = sm + 32768 + s * 4096;

        // ---- store current tile ----
        {
            uint32_t boff = (uint32_t)((r0 << 7) | (j << 4));
            *reinterpret_cast<uint4*>(Bp + SWZ(boff)) = bv;
            uint32_t a0 = (uint32_t)(((r0 +  0) << 7) | (j << 4));
            uint32_t a1 = (uint32_t)(((r0 + 32) << 7) | (j << 4));
            uint32_t a2 = (uint32_t)(((r0 + 64) << 7) | (j << 4));
            uint32_t a3 = (uint32_t)(((r0 + 96) << 7) | (j << 4));
            *reinterpret_cast<uint4*>(Ap + SWZ(a0)) = w[0];
            *reinterpret_cast<uint4*>(Ap + SWZ(a1)) = w[1];
            *reinterpret_cast<uint4*>(Ap + SWZ(a2)) = w[2];
            *reinterpret_cast<uint4*>(Ap + SWZ(a3)) = w[3];
        }
        __syncthreads();

        // ---- prefetch next tile into registers (latency hidden by MMAs below) ----
        const bool more = (it + 1 < NIT);
        uint4 wn0, wn1, wn2, wn3, bvn;
        if (more) {
            wn0 = __ldg(&cbu[qn[0]]);
            wn1 = __ldg(&cbu[qn[1]]);
            wn2 = __ldg(&cbu[qn[2]]);
            wn3 = __ldg(&cbu[qn[3]]);
            bvn = *reinterpret_cast<const uint4*>(
                xh + (size_t)r0 * IN_F + kbase + (it + 1) * 64 + j * 8);
        }
        int qn2[4];
        if (it + 2 < NIT) {
            int g2 = (kbase + (it + 2) * 64) >> 3;
            qn2[0] = __ldg(qrow + g2);
            qn2[1] = __ldg(qrow + g2 + 32 * GROUPS);
            qn2[2] = __ldg(qrow + g2 + 64 * GROUPS);
            qn2[3] = __ldg(qrow + g2 + 96 * GROUPS);
        }

        // ---- MMAs on buffer s ----
        const uint32_t Ab = sb + s * 16384;
        const uint32_t Bb = sb + 32768u + s * 4096;
        const int wM = wid * 16;
        #pragma unroll
        for (int k16 = 0; k16 < 4; ++k16) {
            uint32_t a0r, a1r, a2r, a3r;
            {
                uint32_t off = (uint32_t)((wM + a_row_in_tile) << 7) +
                               (uint32_t)(k16 * 32 + a_kb_half);
                ldmat_x4(Ab + SWZ(off), a0r, a1r, a2r, a3r);
            }
            // B: two x4 loads cover n-tiles {0,1} and {2,3}
            uint32_t b00, b01, b10, b11, b20, b21, b30, b31;
            {
                uint32_t off0 = b_base + (uint32_t)(k16 * 32);
                ldmat_x4(Bb + SWZ(off0), b00, b01, b10, b11);
                uint32_t off1 = off0 + (16u << 7);   // n + 16 rows
                ldmat_x4(Bb + SWZ(off1), b20, b21, b30, b31);
            }
            mma16816(c[0], a0r, a1r, a2r, a3r, b00, b01);
            mma16816(c[1], a0r, a1r, a2r, a3r, b10, b11);
            mma16816(c[2], a0r, a1r, a2r, a3r, b20, b21);
            mma16816(c[3], a0r, a1r, a2r, a3r, b30, b31);
        }

        // rotate pipeline registers
        if (more) {
            w[0] = wn0; w[1] = wn1; w[2] = wn2; w[3] = wn3;
            bv = bvn;
            qn[0] = qn2[0]; qn[1] = qn2[1]; qn[2] = qn2[2]; qn[3] = qn2[3];
        }
    }

    // ---- epilogue: scatter accumulators to z partials ----
    // m16n8 f32 acc: c0,c1 -> row=lid>>2, cols (lid&3)*2,+1 ; c2,c3 -> row+8
    float* zp = g_zpart[blockIdx.y];
    const int row0 = m0 + wid * 16 + (lid >> 2);
    const int col0 = (lid & 3) * 2;
    #pragma unroll
    for (int g = 0; g < 4; ++g) {
        int t0 = g * 8 + col0;
        zp[(size_t)(t0    ) * OUT_F + row0    ] = c[g][0];
        zp[(size_t)(t0 + 1) * OUT_F + row0    ] = c[g][1];
        zp[(size_t)(t0    ) * OUT_F + row0 + 8] = c[g][2];
        zp[(size_t)(t0 + 1) * OUT_F + row0 + 8] = c[g][3];
    }
}

// ---------------- K3: out = fwht(sum z)/sqrt(n) * SV * Wscale ----------------
__global__ void __launch_bounds__(256) k_out(const float* __restrict__ SV,
                                             const float* __restrict__ Wscale,
                                             float* __restrict__ out) {
    __shared__ float s[OUT_F];
    int t = blockIdx.x;
    const float* z0 = g_zpart[0] + (size_t)t * OUT_F;
    const float* z1 = g_zpart[1] + (size_t)t * OUT_F;
    const float* z2 = g_zpart[2] + (size_t)t * OUT_F;
    const float* z3 = g_zpart[3] + (size_t)t * OUT_F;
    for (int i = threadIdx.x; i < OUT_F; i += 256)
        s[i] = (z0[i] + z1[i]) + (z2[i] + z3[i]);
    for (int h = 1; h < OUT_F; h <<= 1) {
        __syncthreads();
        for (int p = threadIdx.x; p < OUT_F / 2; p += 256) {
            int i = 2 * p - (p & (h - 1));
            float a = s[i], b = s[i + h];
            s[i] = a + b;
            s[i + h] = a - b;
        }
    }
    __syncthreads();
    const float ws = Wscale[0] * 0.011048543456039806f;   // Wscale / sqrt(8192)
    float* orow = out + (size_t)t * OUT_F;
    for (int i = threadIdx.x; i < OUT_F; i += 256)
        orow[i] = s[i] * ws * SV[i];
}

// ---------------- launch ----------------
extern "C" void kernel_launch(void* const* d_in, const int* in_sizes, int n_in,
                              void* d_out, int out_size) {
    const float* x      = (const float*)d_in[0];
    const float* cb     = (const float*)d_in[1];
    const int*   qidx   = (const int*)  d_in[2];
    const float* SU     = (const float*)d_in[3];
    const float* SV     = (const float*)d_in[4];
    const float* Wscale = (const float*)d_in[5];
    float* out = (float*)d_out;

    k_cb<<<NCODE / 256, 256>>>(cb);
    k_xh<<<NTOK, 256>>>(x, SU);
    k_main<<<dim3(OUT_F / 128, KSPLIT), 256>>>(qidx);
    k_out<<<NTOK, 256>>>(SV, Wscale, out);
}

// round 5
// speedup vs baseline: 1.2136x; 1.2136x over previous
#include <cuda_runtime.h>
#include <cuda_fp16.h>
#include <cstdint>

#define IN_F   8192
#define OUT_F  8192
#define NTOK   32
#define NCODE  65536
#define GROUPS (IN_F / 8)   // 1024
#define KSPLIT 4
#define KSEG   (IN_F / KSPLIT)   // 2048
#define NIT    (KSEG / 64)       // 32
#define NCHUNK 8                 // 8192 = 8 x 1024

// ---------------- device scratch (no allocations allowed) ----------------
__device__ __align__(16) static __half g_cb16[NCODE * 8];        // 1 MB
__device__ __align__(16) static __half g_xh16[NTOK * IN_F];      // 512 KB
__device__ static float g_zpart[KSPLIT][NTOK * OUT_F];           // 4 MB
__device__ static float g_tmp[NTOK * IN_F];                      // 1 MB (FWHT mid)

// ---------------- helpers ----------------
__device__ __forceinline__ uint32_t smem_u32(const void* p) {
    uint32_t a;
    asm("{ .reg .u64 t; cvta.to.shared.u64 t, %1; cvt.u32.u64 %0, t; }"
        : "=r"(a) : "l"(p));
    return a;
}

#define SWZ(off) ((off) ^ (((off) >> 3) & 0x70))

__device__ __forceinline__ void ldmat_x4(uint32_t addr, uint32_t& r0, uint32_t& r1,
                                         uint32_t& r2, uint32_t& r3) {
    asm volatile("ldmatrix.sync.aligned.m8n8.x4.shared.b16 {%0,%1,%2,%3}, [%4];"
                 : "=r"(r0), "=r"(r1), "=r"(r2), "=r"(r3) : "r"(addr));
}
__device__ __forceinline__ void mma16816(float* c, uint32_t a0, uint32_t a1,
                                         uint32_t a2, uint32_t a3,
                                         uint32_t b0, uint32_t b1) {
    asm volatile("mma.sync.aligned.m16n8k16.row.col.f32.f16.f16.f32 "
                 "{%0,%1,%2,%3}, {%4,%5,%6,%7}, {%8,%9}, {%0,%1,%2,%3};"
                 : "+f"(c[0]), "+f"(c[1]), "+f"(c[2]), "+f"(c[3])
                 : "r"(a0), "r"(a1), "r"(a2), "r"(a3), "r"(b0), "r"(b1));
}

// In-smem FWHT over 1024 floats, 256 threads.
__device__ __forceinline__ void fwht1024(float* s, int tid) {
    for (int h = 1; h < 1024; h <<= 1) {
        __syncthreads();
        #pragma unroll
        for (int pp = 0; pp < 2; ++pp) {
            int p = tid + pp * 256;
            int i = 2 * p - (p & (h - 1));
            float a = s[i], b = s[i + h];
            s[i] = a + b;
            s[i + h] = a - b;
        }
    }
    __syncthreads();
}

// 8-point in-register FWHT
__device__ __forceinline__ void fwht8(float* v) {
    #pragma unroll
    for (int h = 1; h < 8; h <<= 1)
        #pragma unroll
        for (int c = 0; c < 8; ++c)
            if (!(c & h)) {
                float a = v[c], b = v[c + h];
                v[c] = a + b;
                v[c + h] = a - b;
            }
}

// ---------------- K_pre: fused codebook convert + FWHT stage 1 ----------------
// blocks [0,256): codebook fp32->fp16 (one row per thread)
// blocks [256,512): per (token,chunk) H_1024 of x*SU -> g_tmp
__global__ void __launch_bounds__(256) k_pre(const float* __restrict__ cb,
                                             const float* __restrict__ x,
                                             const float* __restrict__ SU) {
    if (blockIdx.x < 256) {
        int r = blockIdx.x * 256 + threadIdx.x;
        const float4* p = reinterpret_cast<const float4*>(cb + (size_t)r * 8);
        float4 a = p[0], b = p[1];
        __half2 h0 = __floats2half2_rn(a.x, a.y);
        __half2 h1 = __floats2half2_rn(a.z, a.w);
        __half2 h2 = __floats2half2_rn(b.x, b.y);
        __half2 h3 = __floats2half2_rn(b.z, b.w);
        uint4 v;
        v.x = *reinterpret_cast<unsigned*>(&h0);
        v.y = *reinterpret_cast<unsigned*>(&h1);
        v.z = *reinterpret_cast<unsigned*>(&h2);
        v.w = *reinterpret_cast<unsigned*>(&h3);
        *reinterpret_cast<uint4*>(g_cb16 + (size_t)r * 8) = v;
        return;
    }
    __shared__ float s[1024];
    int bb = blockIdx.x - 256;        // 0..255
    int t = bb >> 3;                  // token
    int ch = bb & 7;                  // chunk
    size_t base = (size_t)t * IN_F + ch * 1024;
    int tid = threadIdx.x;
    #pragma unroll
    for (int pp = 0; pp < 4; ++pp) {
        int i = tid + pp * 256;
        s[i] = x[base + i] * SU[ch * 1024 + i];
    }
    fwht1024(s, tid);
    #pragma unroll
    for (int pp = 0; pp < 4; ++pp) {
        int i = tid + pp * 256;
        g_tmp[base + i] = s[i];
    }
}

// ---------------- K_xh2: FWHT stage 2 (H_8 across chunks) -> fp16 xh ----------------
__global__ void __launch_bounds__(256) k_xh2() {
    int gid = blockIdx.x * 256 + threadIdx.x;   // 0..32767
    int t = gid >> 10;
    int i = gid & 1023;
    size_t base = (size_t)t * IN_F + i;
    float v[8];
    #pragma unroll
    for (int c = 0; c < 8; ++c) v[c] = g_tmp[base + c * 1024];
    fwht8(v);
    const float sc = 0.011048543456039806f;   // 1/sqrt(8192)
    #pragma unroll
    for (int c = 0; c < 8; ++c)
        g_xh16[base + c * 1024] = __float2half(v[c] * sc);
}

// ---------------- K2: gather-dequant + mma.sync ----------------
__global__ void __launch_bounds__(256) k_main(const int* __restrict__ Qidxs) {
    __shared__ __align__(128) unsigned char sm[40960]; // A0,A1 @0/16384; B0,B1 @32768/36864
    const uint32_t sb = smem_u32(sm);
    const int tid = threadIdx.x;
    const int wid = tid >> 5;
    const int lid = tid & 31;
    const int m0 = blockIdx.x * 128;
    const int kbase = blockIdx.y * KSEG;

    const uint4* __restrict__ cbu = reinterpret_cast<const uint4*>(g_cb16);
    const __half* __restrict__ xh = g_xh16;

    const int r0 = tid >> 3;   // 0..31 (row slot & token)
    const int j  = tid & 7;    // 0..7  (16B column within 128B row)

    float c[4][4];
    #pragma unroll
    for (int g = 0; g < 4; ++g)
        #pragma unroll
        for (int i = 0; i < 4; ++i) c[g][i] = 0.0f;

    int q[4], qn[4];
    uint4 w[4];
    uint4 bv;

    const int* qrow = Qidxs + (size_t)(m0 + r0) * GROUPS + j;

    {
        int g0 = (kbase) >> 3;
        q[0] = __ldg(qrow + g0);
        q[1] = __ldg(qrow + g0 + 32 * GROUPS);
        q[2] = __ldg(qrow + g0 + 64 * GROUPS);
        q[3] = __ldg(qrow + g0 + 96 * GROUPS);
        w[0] = __ldg(&cbu[q[0]]);
        w[1] = __ldg(&cbu[q[1]]);
        w[2] = __ldg(&cbu[q[2]]);
        w[3] = __ldg(&cbu[q[3]]);
        bv = *reinterpret_cast<const uint4*>(xh + (size_t)r0 * IN_F + kbase + j * 8);
        int g1 = (kbase + 64) >> 3;
        qn[0] = __ldg(qrow + g1);
        qn[1] = __ldg(qrow + g1 + 32 * GROUPS);
        qn[2] = __ldg(qrow + g1 + 64 * GROUPS);
        qn[3] = __ldg(qrow + g1 + 96 * GROUPS);
    }

    const int a_row_in_tile = (lid & 7) + ((lid >> 3) & 1) * 8;     // 0..15
    const int a_kb_half     = ((lid >> 4) & 1) * 16;                // byte 0/16
    const int b_mat  = lid >> 3;                                    // 0..3
    const int b_nrow = ((b_mat >> 1) * 8) + (lid & 7);              // 0..15
    const int b_kb   = (b_mat & 1) * 16;                            // byte 0/16
    const uint32_t b_base = ((uint32_t)b_nrow << 7) + (uint32_t)b_kb;

    for (int it = 0; it < NIT; ++it) {
        const int s = it & 1;
        unsigned char* Ap = sm + s * 16384;
        unsigned char* Bp = sm + 32768 + s * 4096;

        {
            uint32_t boff = (uint32_t)((r0 << 7) | (j << 4));
            *reinterpret_cast<uint4*>(Bp + SWZ(boff)) = bv;
            uint32_t a0 = (uint32_t)(((r0 +  0) << 7) | (j << 4));
            uint32_t a1 = (uint32_t)(((r0 + 32) << 7) | (j << 4));
            uint32_t a2 = (uint32_t)(((r0 + 64) << 7) | (j << 4));
            uint32_t a3 = (uint32_t)(((r0 + 96) << 7) | (j << 4));
            *reinterpret_cast<uint4*>(Ap + SWZ(a0)) = w[0];
            *reinterpret_cast<uint4*>(Ap + SWZ(a1)) = w[1];
            *reinterpret_cast<uint4*>(Ap + SWZ(a2)) = w[2];
            *reinterpret_cast<uint4*>(Ap + SWZ(a3)) = w[3];
        }
        __syncthreads();

        const bool more = (it + 1 < NIT);
        uint4 wn0, wn1, wn2, wn3, bvn;
        if (more) {
            wn0 = __ldg(&cbu[qn[0]]);
            wn1 = __ldg(&cbu[qn[1]]);
            wn2 = __ldg(&cbu[qn[2]]);
            wn3 = __ldg(&cbu[qn[3]]);
            bvn = *reinterpret_cast<const uint4*>(
                xh + (size_t)r0 * IN_F + kbase + (it + 1) * 64 + j * 8);
        }
        int qn2[4];
        if (it + 2 < NIT) {
            int g2 = (kbase + (it + 2) * 64) >> 3;
            qn2[0] = __ldg(qrow + g2);
            qn2[1] = __ldg(qrow + g2 + 32 * GROUPS);
            qn2[2] = __ldg(qrow + g2 + 64 * GROUPS);
            qn2[3] = __ldg(qrow + g2 + 96 * GROUPS);
        }

        const uint32_t Ab = sb + s * 16384;
        const uint32_t Bb = sb + 32768u + s * 4096;
        const int wM = wid * 16;
        #pragma unroll
        for (int k16 = 0; k16 < 4; ++k16) {
            uint32_t a0r, a1r, a2r, a3r;
            {
                uint32_t off = (uint32_t)((wM + a_row_in_tile) << 7) +
                               (uint32_t)(k16 * 32 + a_kb_half);
                ldmat_x4(Ab + SWZ(off), a0r, a1r, a2r, a3r);
            }
            uint32_t b00, b01, b10, b11, b20, b21, b30, b31;
            {
                uint32_t off0 = b_base + (uint32_t)(k16 * 32);
                ldmat_x4(Bb + SWZ(off0), b00, b01, b10, b11);
                uint32_t off1 = off0 + (16u << 7);   // n + 16 rows
                ldmat_x4(Bb + SWZ(off1), b20, b21, b30, b31);
            }
            mma16816(c[0], a0r, a1r, a2r, a3r, b00, b01);
            mma16816(c[1], a0r, a1r, a2r, a3r, b10, b11);
            mma16816(c[2], a0r, a1r, a2r, a3r, b20, b21);
            mma16816(c[3], a0r, a1r, a2r, a3r, b30, b31);
        }

        if (more) {
            w[0] = wn0; w[1] = wn1; w[2] = wn2; w[3] = wn3;
            bv = bvn;
            qn[0] = qn2[0]; qn[1] = qn2[1]; qn[2] = qn2[2]; qn[3] = qn2[3];
        }
    }

    float* zp = g_zpart[blockIdx.y];
    const int row0 = m0 + wid * 16 + (lid >> 2);
    const int col0 = (lid & 3) * 2;
    #pragma unroll
    for (int g = 0; g < 4; ++g) {
        int t0 = g * 8 + col0;
        zp[(size_t)(t0    ) * OUT_F + row0    ] = c[g][0];
        zp[(size_t)(t0 + 1) * OUT_F + row0    ] = c[g][1];
        zp[(size_t)(t0    ) * OUT_F + row0 + 8] = c[g][2];
        zp[(size_t)(t0 + 1) * OUT_F + row0 + 8] = c[g][3];
    }
}

// ---------------- K_out1: sum zparts + FWHT stage 1 (H_1024) ----------------
__global__ void __launch_bounds__(256) k_out1() {
    __shared__ float s[1024];
    int t = blockIdx.x >> 3;          // token
    int ch = blockIdx.x & 7;          // chunk
    size_t base = (size_t)t * OUT_F + ch * 1024;
    int tid = threadIdx.x;
    #pragma unroll
    for (int pp = 0; pp < 4; ++pp) {
        int i = tid + pp * 256;
        s[i] = (g_zpart[0][base + i] + g_zpart[1][base + i]) +
               (g_zpart[2][base + i] + g_zpart[3][base + i]);
    }
    fwht1024(s, tid);
    #pragma unroll
    for (int pp = 0; pp < 4; ++pp) {
        int i = tid + pp * 256;
        g_tmp[base + i] = s[i];
    }
}

// ---------------- K_out2: FWHT stage 2 (H_8) * SV * Wscale -> out ----------------
__global__ void __launch_bounds__(256) k_out2(const float* __restrict__ SV,
                                              const float* __restrict__ Wscale,
                                              float* __restrict__ out) {
    int gid = blockIdx.x * 256 + threadIdx.x;   // 0..32767
    int t = gid >> 10;
    int i = gid & 1023;
    size_t base = (size_t)t * OUT_F + i;
    float v[8];
    #pragma unroll
    for (int c = 0; c < 8; ++c) v[c] = g_tmp[base + c * 1024];
    fwht8(v);
    const float ws = Wscale[0] * 0.011048543456039806f;   // Wscale / sqrt(8192)
    #pragma unroll
    for (int c = 0; c < 8; ++c)
        out[base + c * 1024] = v[c] * ws * SV[i + c * 1024];
}

// ---------------- launch ----------------
extern "C" void kernel_launch(void* const* d_in, const int* in_sizes, int n_in,
                              void* d_out, int out_size) {
    const float* x      = (const float*)d_in[0];
    const float* cb     = (const float*)d_in[1];
    const int*   qidx   = (const int*)  d_in[2];
    const float* SU     = (const float*)d_in[3];
    const float* SV     = (const float*)d_in[4];
    const float* Wscale = (const float*)d_in[5];
    float* out = (float*)d_out;

    k_pre<<<512, 256>>>(cb, x, SU);
    k_xh2<<<NTOK * 1024 / 256, 256>>>();
    k_main<<<dim3(OUT_F / 128, KSPLIT), 256>>>(qidx);
    k_out1<<<NTOK * NCHUNK, 256>>>();
    k_out2<<<NTOK * 1024 / 256, 256>>>(SV, Wscale, out);
}